// round 11
// baseline (speedup 1.0000x reference)
#include <cuda_runtime.h>
#include <cuda_fp16.h>
#include <cstdint>

// Problem constants
#define NN   24
#define EE   96
#define BB   4
#define CC   8
#define HH   96
#define WW   96
#define KK   4
#define HW    (HH*WW)
#define CHW   (CC*HW)
#define BCHW  (BB*CHW)

// Padded fp16 activation scratch, ci-pair interleaved (+ tail pad for staging)
#define PH 100
#define PW 100
#define PLANE (PH*PW)            // 10000 words
#define NACTW (25*BB*4*PLANE + 4096)

// Conv-MMA tiling (fp16 m16n8k16, 2 kx taps per MMA, permuted rows)
#define SEGPX  640               // pixels per item (40 m16 tiles); 15*640=9600 exact
#define NSEG   15
#define TPW    5                 // m16 tiles per warp (8 warps)
#define WINW   944               // window words per cpair plane
#define PSTR   968               // cpair stride in words (==8 mod 32)
#define ABUF   (4*PSTR)          // 3872 words per stage buffer
#define PAIR4  236               // uint4 chunks per cpair window
#define NITEM  (NSEG*BB*NN)      // 1440 work items
#define NPBLK  592               // persistent blocks (148 SM x 4)

__device__ __align__(16) unsigned int g_act[NACTW];
__device__ __align__(16) unsigned int g_bpack[EE * 32 * 16];
__device__ int   g_off[NN + 1];
__device__ int   g_elist[EE];
__device__ float g_escale[EE];
__device__ float g_postsum[NN];
__device__ unsigned int g_done;
__device__ unsigned int g_wq;

__device__ __forceinline__ void mma_f16(float* d, uint32_t a0, uint32_t a1,
                                        uint32_t a2, uint32_t a3,
                                        uint32_t b0, uint32_t b1) {
    asm volatile(
        "mma.sync.aligned.m16n8k16.row.col.f32.f16.f16.f32 "
        "{%0,%1,%2,%3}, {%4,%5,%6,%7}, {%8,%9}, {%0,%1,%2,%3};"
        : "+f"(d[0]), "+f"(d[1]), "+f"(d[2]), "+f"(d[3])
        : "r"(a0), "r"(a1), "r"(a2), "r"(a3), "r"(b0), "r"(b1));
}

__device__ __forceinline__ void cpa16(uint32_t dst, const void* src) {
    asm volatile("cp.async.cg.shared.global [%0], [%1], 16;"
                 :: "r"(dst), "l"(src));
}
__device__ __forceinline__ uint32_t smem_u32(const void* p) {
    uint32_t a;
    asm("{ .reg .u64 t; cvta.to.shared.u64 t, %1; cvt.u32.u64 %0, t; }"
        : "=r"(a) : "l"(p));
    return a;
}
__device__ __forceinline__ uint32_t h2pack(float lo, float hi) {
    __half2 h = __floats2half2_rn(lo, hi);
    return *reinterpret_cast<uint32_t*>(&h);
}
__device__ __forceinline__ float fast_sigmoid(float x) {
    float th;
    asm("tanh.approx.f32 %0, %1;" : "=f"(th) : "f"(x * 0.5f));
    return fmaf(th, 0.5f, 0.5f);
}

// ---------------------------------------------------------------------------
// Activation precompute (+ edge prep + queue reset in block (0,0)).
// grid = (9, 400). Thread -> 4 consecutive pixels of one cpair plane.
// ---------------------------------------------------------------------------
__global__ __launch_bounds__(256)
void act_prep_kernel(const float* __restrict__ states,
                     const int* __restrict__ dst,
                     const float* __restrict__ plast) {
    const int t = threadIdx.x;
    if (blockIdx.x == 0 && blockIdx.y == 0) {
        __shared__ int cnt[NN];
        __shared__ int fill[NN];
        if (t < NN) { cnt[t] = 0; g_postsum[t] = 0.0f; }
        if (t == 0) { g_wq = 0u; g_done = 0u; }
        __syncthreads();
        if (t < EE) atomicAdd(&cnt[dst[t]], 1);
        __syncthreads();
        if (t == 0) {
            int off = 0;
            for (int n = 0; n < NN; ++n) { g_off[n] = off; fill[n] = off; off += cnt[n]; }
            g_off[NN] = off;
        }
        __syncthreads();
        if (t < EE) {
            int d = dst[t];
            int pos = atomicAdd(&fill[d], 1);
            g_elist[pos] = t;
            int deg = cnt[d] > 0 ? cnt[d] : 1;
            g_escale[t] = plast[t] / (float)deg;
        }
    }
    const int gp = blockIdx.y;              // group*4 + cp
    const int grp = gp >> 2;
    const int cp = gp & 3;
    const int pix = (blockIdx.x * 256 + t) * 4;
    const int r = pix / 96;
    const int c = pix - r * 96;

    const size_t base = (size_t)(grp * CC + 2 * cp) * HW + r * WW + c;
    const float4 zl = *reinterpret_cast<const float4*>(states + base);
    const float4 zh = *reinterpret_cast<const float4*>(states + base + HW);

    unsigned int* op = g_act + (size_t)gp * PLANE + (r + 1) * PW + 1 + c;
    op[0] = h2pack(fast_sigmoid(zl.x), fast_sigmoid(zh.x));
    op[1] = h2pack(fast_sigmoid(zl.y), fast_sigmoid(zh.y));
    op[2] = h2pack(fast_sigmoid(zl.z), fast_sigmoid(zh.z));
    op[3] = h2pack(fast_sigmoid(zl.w), fast_sigmoid(zh.w));
}

// ---------------------------------------------------------------------------
// B-fragment prepack (per edge, per lane, register order).
// ---------------------------------------------------------------------------
__global__ void prepack_kernel(const float* __restrict__ weights) {
    const int e = blockIdx.x;
    const int l = threadIdx.x;
    const int g = l >> 2;
    const int tg = l & 3;
    const float esc = g_escale[e];
    const float* wg = weights + (size_t)e * (CC * CC * KK * KK);
    const float4* rA = reinterpret_cast<const float4*>(wg + (g * CC + 2 * tg) * 16);
    const float4* rB = reinterpret_cast<const float4*>(wg + (g * CC + 2 * tg + 1) * 16);
    uint32_t o[16];
#pragma unroll
    for (int ky = 0; ky < 4; ++ky) {
        float4 a = rA[ky];
        float4 b = rB[ky];
        o[ky * 4 + 0] = h2pack(a.x * esc, b.x * esc);
        o[ky * 4 + 1] = h2pack(a.y * esc, b.y * esc);
        o[ky * 4 + 2] = h2pack(a.z * esc, b.z * esc);
        o[ky * 4 + 3] = h2pack(a.w * esc, b.w * esc);
    }
    uint4* dstp = reinterpret_cast<uint4*>(g_bpack + ((size_t)e * 32 + l) * 16);
#pragma unroll
    for (int j = 0; j < 4; ++j)
        dstp[j] = make_uint4(o[j * 4], o[j * 4 + 1], o[j * 4 + 2], o[j * 4 + 3]);
}

// ---------------------------------------------------------------------------
// Persistent conv kernel: 592 blocks steal items from a global queue.
// Item i -> (n = i/60, b = (i%60)/15, seg = i%15).
// ---------------------------------------------------------------------------
extern __shared__ unsigned int s_dynw[];

__global__ __launch_bounds__(256, 4)
void conv_mma_kernel(const int* __restrict__ src,
                     const float* __restrict__ plast,
                     const int* __restrict__ dst,
                     float* __restrict__ out,
                     float* __restrict__ outp) {
    __shared__ float s_red[8];
    __shared__ int s_item;
    __shared__ int s_last;
    unsigned int* s_win = s_dynw;
    const uint32_t s_win_u32 = smem_u32(s_win);

    const int t = threadIdx.x;
    const int w = t >> 5;
    const int l = t & 31;
    const int gid = l >> 2;
    const int tig = l & 3;

    for (;;) {
        if (t == 0) s_item = (int)atomicAdd(&g_wq, 1u);
        __syncthreads();
        const int item = s_item;
        if (item >= NITEM) break;

        const int n = item / (NSEG * BB);
        const int rem = item - n * (NSEG * BB);
        const int b = rem / NSEG;
        const int seg = rem - b * NSEG;
        const int qbase = seg * SEGPX;

        float d[TPW][4];
#pragma unroll
        for (int u = 0; u < TPW; ++u)
#pragma unroll
            for (int j = 0; j < 4; ++j) d[u][j] = 0.0f;

        const int ebeg = g_off[n];
        const int eend = g_off[n + 1];

        auto stage = [&](int e, uint32_t dbase) {
            const int s = __ldg(&src[e]);
            const uint4* ap = reinterpret_cast<const uint4*>(
                g_act + ((size_t)(s * BB + b) * 4) * PLANE + qbase);
#pragma unroll
            for (int cp = 0; cp < 4; ++cp)
                for (int i = t; i < PAIR4; i += 256)
                    cpa16(dbase + (cp * PSTR + i * 4) * 4,
                          ap + cp * (PLANE / 4) + i);
            asm volatile("cp.async.commit_group;");
        };

        stage(g_elist[ebeg], s_win_u32);

        for (int ei = ebeg; ei < eend; ++ei) {
            const int p = (ei - ebeg) & 1;
            const int e = g_elist[ei];

            const uint4* bp = reinterpret_cast<const uint4*>(
                g_bpack + ((size_t)e * 32 + l) * 16);
            uint4 bq[4];
#pragma unroll
            for (int ky = 0; ky < 4; ++ky) bq[ky] = __ldg(&bp[ky]);

            asm volatile("cp.async.wait_group 0;");
            __syncthreads();

            if (ei + 1 < eend)
                stage(g_elist[ei + 1], s_win_u32 + (1 - p) * (ABUF * 4));

            const unsigned int* fbase = s_win + p * ABUF + tig * PSTR + 2 * gid;
#pragma unroll
            for (int ky = 0; ky < KK; ++ky) {
                const uint32_t b00 = bq[ky].x, b01 = bq[ky].y;
                const uint32_t b10 = bq[ky].z, b11 = bq[ky].w;
#pragma unroll
                for (int kxp = 0; kxp < 2; ++kxp) {
                    const uint32_t bb0 = kxp ? b10 : b00;
                    const uint32_t bb1 = kxp ? b11 : b01;
                    const int o = ky * PW + kxp * 2;
#pragma unroll
                    for (int u = 0; u < TPW; ++u) {
                        const unsigned int* pa = fbase + (w * TPW + u) * 16 + o;
                        const uint2 v = *reinterpret_cast<const uint2*>(pa);
                        const uint32_t a3 = pa[2];
                        mma_f16(d[u], v.x, v.y, v.y, a3, bb0, bb1);
                    }
                }
            }
        }

        // Epilogue: pixel pair (q0, q0+1); only x mask needed (y<96 always)
        float ls = 0.0f;
        const int co0 = tig * 2;
        float* outn = out + (size_t)((n * BB + b) * CC) * HW;
#pragma unroll
        for (int u = 0; u < TPW; ++u) {
            const int q0 = qbase + (w * TPW + u) * 16 + 2 * gid;
            const int y = q0 / PW;
            const int x = q0 - y * PW;
            if (x < WW) {
                float v00 = d[u][0], v01 = d[u][1];
                float v10 = d[u][2], v11 = d[u][3];
                float* ob = outn + y * WW + x;
                ob[(size_t)co0 * HW] = v00;
                ob[(size_t)(co0 + 1) * HW] = v01;
                ob[(size_t)co0 * HW + 1] = v10;
                ob[(size_t)(co0 + 1) * HW + 1] = v11;
                ls += fast_sigmoid(v00);
                ls += fast_sigmoid(v01);
                ls += fast_sigmoid(v10);
                ls += fast_sigmoid(v11);
            }
        }
#pragma unroll
        for (int o = 16; o > 0; o >>= 1) ls += __shfl_down_sync(0xffffffffu, ls, o);
        if (l == 0) s_red[w] = ls;
        __syncthreads();
        if (t == 0) {
            float sum = 0.0f;
#pragma unroll
            for (int i = 0; i < 8; ++i) sum += s_red[i];
            atomicAdd(&g_postsum[n], sum);
            __threadfence();
            unsigned prev = atomicAdd(&g_done, 1u);
            s_last = (prev == NITEM - 1) ? 1 : 0;
        }
        __syncthreads();
        if (s_last && t < EE) {
            float mean = g_postsum[dst[t]] * (1.0f / (float)BCHW);
            outp[t] = plast[t] + 0.1f * (mean - 0.5f);
        }
        __syncthreads();   // all warps past epilogue before next item's staging
    }
}

// ---------------------------------------------------------------------------
extern "C" void kernel_launch(void* const* d_in, const int* in_sizes, int n_in,
                              void* d_out, int out_size) {
    const float* states  = (const float*)d_in[0];
    const float* weights = (const float*)d_in[1];
    const float* plast   = (const float*)d_in[2];
    const int*   src     = (const int*)d_in[3];
    const int*   dst     = (const int*)d_in[4];
    float* out = (float*)d_out;

    dim3 agrid(9, 400);
    act_prep_kernel<<<agrid, 256>>>(states, dst, plast);
    prepack_kernel<<<EE, 32>>>(weights);

    static int smem_set = 0;
    const int smem_bytes = 2 * ABUF * 4;     // 30976 B
    if (!smem_set) {
        cudaFuncSetAttribute(conv_mma_kernel,
                             cudaFuncAttributeMaxDynamicSharedMemorySize,
                             smem_bytes);
        smem_set = 1;
    }
    conv_mma_kernel<<<NPBLK, 256, smem_bytes>>>(src, plast, dst, out,
                                                out + (out_size - EE));
}

// round 12
// speedup vs baseline: 1.0928x; 1.0928x over previous
#include <cuda_runtime.h>
#include <cuda_fp16.h>
#include <cstdint>

// Problem constants
#define NN   24
#define EE   96
#define BB   4
#define CC   8
#define HH   96
#define WW   96
#define KK   4
#define HW    (HH*WW)
#define CHW   (CC*HW)
#define BCHW  (BB*CHW)

// Padded fp16 activation scratch, ci-pair interleaved (+ tail pad for staging)
#define PH 100
#define PW 100
#define PLANE (PH*PW)            // 10000 words
#define NACTW (25*BB*4*PLANE + 4096)

// Conv-MMA tiling (fp16 m16n8k16, 2 kx taps per MMA, permuted rows)
#define SEGPX  640               // pixels per block (40 m16 tiles); 15*640=9600
#define NSEG   15
#define TPW    5                 // m16 tiles per warp (8 warps)
#define WINW   944               // window words per cpair plane
#define PSTR   968               // cpair stride in words (==8 mod 32)
#define ABUF   (4*PSTR)          // 3872 words per stage buffer
#define PAIR4  236               // uint4 chunks per cpair window
#define NBLK   (NSEG*BB*NN)      // 1440 conv blocks

__device__ __align__(16) unsigned int g_act[NACTW];
__device__ __align__(16) unsigned int g_bpack[EE * 32 * 16];
__device__ int   g_off[NN + 1];
__device__ int   g_elist[EE];
__device__ float g_postsum[NN];
__device__ unsigned int g_done;

__device__ __forceinline__ void mma_f16(float* d, uint32_t a0, uint32_t a1,
                                        uint32_t a2, uint32_t a3,
                                        uint32_t b0, uint32_t b1) {
    asm volatile(
        "mma.sync.aligned.m16n8k16.row.col.f32.f16.f16.f32 "
        "{%0,%1,%2,%3}, {%4,%5,%6,%7}, {%8,%9}, {%0,%1,%2,%3};"
        : "+f"(d[0]), "+f"(d[1]), "+f"(d[2]), "+f"(d[3])
        : "r"(a0), "r"(a1), "r"(a2), "r"(a3), "r"(b0), "r"(b1));
}

__device__ __forceinline__ void cpa16(uint32_t dst, const void* src) {
    asm volatile("cp.async.cg.shared.global [%0], [%1], 16;"
                 :: "r"(dst), "l"(src));
}
__device__ __forceinline__ uint32_t smem_u32(const void* p) {
    uint32_t a;
    asm("{ .reg .u64 t; cvta.to.shared.u64 t, %1; cvt.u32.u64 %0, t; }"
        : "=r"(a) : "l"(p));
    return a;
}
__device__ __forceinline__ uint32_t h2pack(float lo, float hi) {
    __half2 h = __floats2half2_rn(lo, hi);
    return *reinterpret_cast<uint32_t*>(&h);
}
__device__ __forceinline__ float fast_sigmoid(float x) {
    float th;
    asm("tanh.approx.f32 %0, %1;" : "=f"(th) : "f"(x * 0.5f));
    return fmaf(th, 0.5f, 0.5f);
}

// ---------------------------------------------------------------------------
// Fused act + prepack (+ edge-list prep in block (0,0)).
// grid = (10, 400): x<9 -> activation planes; x==9, y<EE -> B prepack.
// ---------------------------------------------------------------------------
__global__ __launch_bounds__(256)
void act_prep_kernel(const float* __restrict__ states,
                     const int* __restrict__ dst,
                     const float* __restrict__ plast,
                     const float* __restrict__ weights) {
    const int t = threadIdx.x;

    if (blockIdx.x == 9) {
        // B-fragment prepack, one edge per block (y<96); degree computed locally
        const int e = blockIdx.y;
        if (e < EE && t < 32) {
            const int de = dst[e];
            int deg = 0;
#pragma unroll 4
            for (int j = 0; j < EE; ++j) deg += (dst[j] == de) ? 1 : 0;
            const float esc = plast[e] / (float)(deg > 0 ? deg : 1);
            const int g = t >> 2;
            const int tg = t & 3;
            const float* wg = weights + (size_t)e * (CC * CC * KK * KK);
            const float4* rA = reinterpret_cast<const float4*>(wg + (g * CC + 2 * tg) * 16);
            const float4* rB = reinterpret_cast<const float4*>(wg + (g * CC + 2 * tg + 1) * 16);
            uint32_t o[16];
#pragma unroll
            for (int ky = 0; ky < 4; ++ky) {
                float4 a = rA[ky];
                float4 b = rB[ky];
                o[ky * 4 + 0] = h2pack(a.x * esc, b.x * esc);
                o[ky * 4 + 1] = h2pack(a.y * esc, b.y * esc);
                o[ky * 4 + 2] = h2pack(a.z * esc, b.z * esc);
                o[ky * 4 + 3] = h2pack(a.w * esc, b.w * esc);
            }
            uint4* dstp = reinterpret_cast<uint4*>(g_bpack + ((size_t)e * 32 + t) * 16);
#pragma unroll
            for (int j = 0; j < 4; ++j)
                dstp[j] = make_uint4(o[j * 4], o[j * 4 + 1], o[j * 4 + 2], o[j * 4 + 3]);
        }
        return;
    }

    if (blockIdx.x == 0 && blockIdx.y == 0) {
        __shared__ int cnt[NN];
        __shared__ int fill[NN];
        if (t < NN) { cnt[t] = 0; g_postsum[t] = 0.0f; }
        if (t == 0) g_done = 0u;
        __syncthreads();
        if (t < EE) atomicAdd(&cnt[dst[t]], 1);
        __syncthreads();
        if (t == 0) {
            int off = 0;
            for (int n = 0; n < NN; ++n) { g_off[n] = off; fill[n] = off; off += cnt[n]; }
            g_off[NN] = off;
        }
        __syncthreads();
        if (t < EE) {
            int pos = atomicAdd(&fill[dst[t]], 1);
            g_elist[pos] = t;
        }
    }

    const int gp = blockIdx.y;              // group*4 + cp
    const int grp = gp >> 2;
    const int cp = gp & 3;
    const int pix = (blockIdx.x * 256 + t) * 4;
    const int r = pix / 96;
    const int c = pix - r * 96;

    const size_t base = (size_t)(grp * CC + 2 * cp) * HW + r * WW + c;
    const float4 zl = *reinterpret_cast<const float4*>(states + base);
    const float4 zh = *reinterpret_cast<const float4*>(states + base + HW);

    unsigned int* op = g_act + (size_t)gp * PLANE + (r + 1) * PW + 1 + c;
    op[0] = h2pack(fast_sigmoid(zl.x), fast_sigmoid(zh.x));
    op[1] = h2pack(fast_sigmoid(zl.y), fast_sigmoid(zh.y));
    op[2] = h2pack(fast_sigmoid(zl.z), fast_sigmoid(zh.z));
    op[3] = h2pack(fast_sigmoid(zl.w), fast_sigmoid(zh.w));
}

// ---------------------------------------------------------------------------
// Conv via fp16 m16n8k16, triple-buffered cp.async (wait_group 1), folded LDS.
// grid = (NSEG, B, N), 256 threads, 4 blocks/SM.
// ---------------------------------------------------------------------------
extern __shared__ unsigned int s_dynw[];

__global__ __launch_bounds__(256, 4)
void conv_mma_kernel(const int* __restrict__ src,
                     const float* __restrict__ plast,
                     const int* __restrict__ dst,
                     float* __restrict__ out,
                     float* __restrict__ outp) {
    const int seg = blockIdx.x;
    const int b = blockIdx.y;
    const int n = blockIdx.z;
    const int qbase = seg * SEGPX;

    __shared__ float s_red[8];
    __shared__ int s_last;
    unsigned int* s_win = s_dynw;                  // [3][ABUF]
    const uint32_t s_win_u32 = smem_u32(s_win);

    const int t = threadIdx.x;
    const int w = t >> 5;
    const int l = t & 31;
    const int gid = l >> 2;
    const int tig = l & 3;

    float d[TPW][4];
#pragma unroll
    for (int u = 0; u < TPW; ++u)
#pragma unroll
        for (int j = 0; j < 4; ++j) d[u][j] = 0.0f;

    const int ebeg = g_off[n];
    const int eend = g_off[n + 1];
    const int cnt = eend - ebeg;

    auto stage = [&](int e, int buf) {
        const int s = __ldg(&src[e]);
        const uint4* ap = reinterpret_cast<const uint4*>(
            g_act + ((size_t)(s * BB + b) * 4) * PLANE + qbase);
        const uint32_t dbase = s_win_u32 + buf * (ABUF * 4);
#pragma unroll
        for (int cp = 0; cp < 4; ++cp)
            for (int i = t; i < PAIR4; i += 256)
                cpa16(dbase + (cp * PSTR + i * 4) * 4,
                      ap + cp * (PLANE / 4) + i);
        asm volatile("cp.async.commit_group;");
    };

    stage(g_elist[ebeg], 0);
    if (cnt > 1) stage(g_elist[ebeg + 1], 1);

    for (int i = 0; i < cnt; ++i) {
        const int e = g_elist[ebeg + i];

        const uint4* bp = reinterpret_cast<const uint4*>(
            g_bpack + ((size_t)e * 32 + l) * 16);
        uint4 bq[4];
#pragma unroll
        for (int ky = 0; ky < 4; ++ky) bq[ky] = __ldg(&bp[ky]);

        if (i + 1 < cnt) { asm volatile("cp.async.wait_group 1;"); }
        else             { asm volatile("cp.async.wait_group 0;"); }
        __syncthreads();

        if (i + 2 < cnt) stage(g_elist[ebeg + i + 2], (i + 2) % 3);

        const unsigned int* fbase = s_win + (i % 3) * ABUF + tig * PSTR + 2 * gid;
#pragma unroll
        for (int ky = 0; ky < KK; ++ky) {
            const uint32_t b00 = bq[ky].x, b01 = bq[ky].y;
            const uint32_t b10 = bq[ky].z, b11 = bq[ky].w;
            const int o = ky * PW;
#pragma unroll
            for (int u = 0; u < TPW; ++u) {
                const unsigned int* pa = fbase + (w * TPW + u) * 16 + o;
                const uint2 va = *reinterpret_cast<const uint2*>(pa);       // o,o+1
                const uint2 vb = *reinterpret_cast<const uint2*>(pa + 2);   // o+2,o+3
                const uint32_t vc = pa[4];                                  // o+4
                mma_f16(d[u], va.x, va.y, va.y, vb.x, b00, b01);  // kxp=0
                mma_f16(d[u], vb.x, vb.y, vb.y, vc, b10, b11);    // kxp=1
            }
        }
    }

    // Epilogue: pixel pair (q0, q0+1); x mask only (y<96 always)
    float ls = 0.0f;
    const int co0 = tig * 2;
    float* outn = out + (size_t)((n * BB + b) * CC) * HW;
#pragma unroll
    for (int u = 0; u < TPW; ++u) {
        const int q0 = qbase + (w * TPW + u) * 16 + 2 * gid;
        const int y = q0 / PW;
        const int x = q0 - y * PW;
        if (x < WW) {
            float v00 = d[u][0], v01 = d[u][1];
            float v10 = d[u][2], v11 = d[u][3];
            float* ob = outn + y * WW + x;
            ob[(size_t)co0 * HW] = v00;
            ob[(size_t)(co0 + 1) * HW] = v01;
            ob[(size_t)co0 * HW + 1] = v10;
            ob[(size_t)(co0 + 1) * HW + 1] = v11;
            ls += fast_sigmoid(v00);
            ls += fast_sigmoid(v01);
            ls += fast_sigmoid(v10);
            ls += fast_sigmoid(v11);
        }
    }
#pragma unroll
    for (int o = 16; o > 0; o >>= 1) ls += __shfl_down_sync(0xffffffffu, ls, o);
    if (l == 0) s_red[w] = ls;
    __syncthreads();
    if (t == 0) {
        float sum = 0.0f;
#pragma unroll
        for (int i = 0; i < 8; ++i) sum += s_red[i];
        atomicAdd(&g_postsum[n], sum);
        __threadfence();
        unsigned prev = atomicAdd(&g_done, 1u);
        s_last = (prev == NBLK - 1) ? 1 : 0;
    }
    __syncthreads();
    if (s_last && t < EE) {
        float mean = g_postsum[dst[t]] * (1.0f / (float)BCHW);
        outp[t] = plast[t] + 0.1f * (mean - 0.5f);
    }
}

// ---------------------------------------------------------------------------
extern "C" void kernel_launch(void* const* d_in, const int* in_sizes, int n_in,
                              void* d_out, int out_size) {
    const float* states  = (const float*)d_in[0];
    const float* weights = (const float*)d_in[1];
    const float* plast   = (const float*)d_in[2];
    const int*   src     = (const int*)d_in[3];
    const int*   dst     = (const int*)d_in[4];
    float* out = (float*)d_out;

    dim3 agrid(10, 400);
    act_prep_kernel<<<agrid, 256>>>(states, dst, plast, weights);

    static int smem_set = 0;
    const int smem_bytes = 3 * ABUF * 4;     // 46464 B
    if (!smem_set) {
        cudaFuncSetAttribute(conv_mma_kernel,
                             cudaFuncAttributeMaxDynamicSharedMemorySize,
                             smem_bytes);
        smem_set = 1;
    }
    dim3 grid(NSEG, BB, NN);
    conv_mma_kernel<<<grid, 256, smem_bytes>>>(src, plast, dst, out,
                                               out + (out_size - EE));
}